// round 1
// baseline (speedup 1.0000x reference)
#include <cuda_runtime.h>
#include <cuda_bf16.h>

#define HH      1024
#define NMODES  64
#define LLEN    2048
#define NCHUNK  32          // l-chunks per head
#define CHUNKLEN 64         // l per chunk
#define TPB     256         // 8 mode-groups x 32 chunks
#define MPT     8           // modes per thread

struct __align__(8) cplx { float r, i; };

__global__ __launch_bounds__(TPB, 4)
void ssd_vandermonde_kernel(
    const float* __restrict__ log_dt,
    const float* __restrict__ log_w_real,
    const float* __restrict__ w_imag,
    const float* __restrict__ C_re,
    const float* __restrict__ C_im,
    float* __restrict__ out)
{
    __shared__ cplx  sZ[NMODES];              // z = exp(dtA)
    __shared__ cplx  sA[NMODES][NCHUNK];      // anchor: 2*Cmod * z^(64*chunk)
    __shared__ float sOut[LLEN];

    const int h   = blockIdx.x;
    const int tid = threadIdx.x;

    // ---------------- Setup: per-mode constants (64 threads) ----------------
    if (tid < NMODES) {
        const int n = tid;
        const float dt  = expf(log_dt[h]);
        const float wr  = -expf(log_w_real[h * NMODES + n]);
        const float wi  = w_imag[h * NMODES + n];
        const float ar  = wr * dt;
        const float ai  = wi * dt;

        // z = exp(dtA)
        float s, c;
        const float ez = expf(ar);
        sincosf(ai, &s, &c);
        const float zr = ez * c;
        const float zi = ez * s;
        sZ[n].r = zr; sZ[n].i = zi;

        // Cmod = C * (z - 1) / w   (fold factor 2 for final 2*Re)
        const float den = wr * wr + wi * wi;
        const float zm1r = zr - 1.0f;
        const float tr = (zm1r * wr + zi * wi) / den;
        const float ti = (zi * wr - zm1r * wi) / den;
        const float cr = C_re[h * NMODES + n];
        const float ci = C_im[h * NMODES + n];
        float ur = 2.0f * (cr * tr - ci * ti);
        float ui = 2.0f * (cr * ti + ci * tr);

        // z^64 computed via exp (ai*64 is an exact fp32 product -> exact phase arg)
        float s64, c64;
        const float e64 = expf(ar * 64.0f);
        sincosf(ai * 64.0f, &s64, &c64);
        const float z64r = e64 * c64;
        const float z64i = e64 * s64;

        // anchor table: A[n][c] = 2*Cmod * z64^c
        sA[n][0].r = ur; sA[n][0].i = ui;
        #pragma unroll 1
        for (int cidx = 1; cidx < NCHUNK; cidx++) {
            const float nr = ur * z64r - ui * z64i;
            const float ni = ur * z64i + ui * z64r;
            ur = nr; ui = ni;
            sA[n][cidx].r = ur; sA[n][cidx].i = ui;
        }
    }
    __syncthreads();

    // ---------------- Main recurrence ----------------
    const int tx    = tid & (MPT - 1);   // 0..7 : mode group
    const int chunk = tid >> 3;          // 0..31 : l chunk
    const int nbase = tx * MPT;

    float ur[MPT], ui[MPT], zr[MPT], zi[MPT];
    #pragma unroll
    for (int j = 0; j < MPT; j++) {
        ur[j] = sA[nbase + j][chunk].r;
        ui[j] = sA[nbase + j][chunk].i;
        zr[j] = sZ[nbase + j].r;
        zi[j] = sZ[nbase + j].i;
    }

    float* so = &sOut[chunk * CHUNKLEN];
    const bool writer = (tx == 0);

    #pragma unroll 8
    for (int d = 0; d < CHUNKLEN; d++) {
        float acc = 0.0f;
        #pragma unroll
        for (int j = 0; j < MPT; j++) {
            acc += ur[j];
            const float nr = ur[j] * zr[j] - ui[j] * zi[j];
            const float ni = ur[j] * zi[j] + ui[j] * zr[j];
            ur[j] = nr; ui[j] = ni;
        }
        // reduce across the 8 mode-groups (lanes differing in low 3 bits)
        acc += __shfl_xor_sync(0xffffffff, acc, 1);
        acc += __shfl_xor_sync(0xffffffff, acc, 2);
        acc += __shfl_xor_sync(0xffffffff, acc, 4);
        if (writer) so[d] = acc;
    }
    __syncthreads();

    // ---------------- Coalesced writeback ----------------
    float4*       o4 = reinterpret_cast<float4*>(out + (size_t)h * LLEN);
    const float4* s4 = reinterpret_cast<const float4*>(sOut);
    #pragma unroll
    for (int k = tid; k < LLEN / 4; k += TPB) {
        o4[k] = s4[k];
    }
}

extern "C" void kernel_launch(void* const* d_in, const int* in_sizes, int n_in,
                              void* d_out, int out_size)
{
    const float* log_dt     = (const float*)d_in[0];
    const float* log_w_real = (const float*)d_in[1];
    const float* w_imag     = (const float*)d_in[2];
    const float* C_re       = (const float*)d_in[3];
    const float* C_im       = (const float*)d_in[4];
    float*       out        = (float*)d_out;

    ssd_vandermonde_kernel<<<HH, TPB>>>(log_dt, log_w_real, w_imag, C_re, C_im, out);
}

// round 2
// speedup vs baseline: 1.3696x; 1.3696x over previous
#include <cuda_runtime.h>
#include <cuda_bf16.h>
#include <cstdint>

#define HH      1024
#define NMODES  64
#define NPAIR   32          // mode pairs
#define LLEN    2048
#define TPB     256         // thread t owns l in [8t, 8t+8)
#define LPT     8           // l per thread

typedef unsigned long long u64;

// ---- packed f32x2 helpers (Blackwell packed fp32) ----
__device__ __forceinline__ u64 f2mul(u64 a, u64 b) {
    u64 d; asm("mul.rn.f32x2 %0,%1,%2;" : "=l"(d) : "l"(a), "l"(b)); return d;
}
__device__ __forceinline__ u64 f2fma(u64 a, u64 b, u64 c) {
    u64 d; asm("fma.rn.f32x2 %0,%1,%2,%3;" : "=l"(d) : "l"(a), "l"(b), "l"(c)); return d;
}
__device__ __forceinline__ u64 f2add(u64 a, u64 b) {
    u64 d; asm("add.rn.f32x2 %0,%1,%2;" : "=l"(d) : "l"(a), "l"(b)); return d;
}
__device__ __forceinline__ uint32_t smem_u32(const void* p) {
    uint32_t a;
    asm("{ .reg .u64 t; cvta.to.shared.u64 t, %1; cvt.u32.u64 %0, t; }" : "=r"(a) : "l"(p));
    return a;
}

__global__ __launch_bounds__(TPB, 4)
void ssd_vandermonde_f32x2_kernel(
    const float* __restrict__ log_dt,
    const float* __restrict__ log_w_real,
    const float* __restrict__ w_imag,
    const float* __restrict__ C_re,
    const float* __restrict__ C_im,
    float* __restrict__ out)
{
    // Per mode-pair k (modes 2k, 2k+1), packed as (lo=mode 2k, hi=mode 2k+1):
    //  Ptab[k][r]    = { Pr0, Pr1, Pi0, Pi1 }          P = z^(8r),   r = 0..31
    //  Qtab[k][q][0] = { Qr0, Qr1, Qi0, Qi1 }          Q = 2*Cmod*z^(256q), q = 0..7
    //  Qtab[k][q][1] = { -Qi0, -Qi1, pad, pad }
    //  Ztab[k]       = { zr0, zr1, -zi0, -zi1 }
    //  PQtab[k]      = { 2zr0, 2zr1, -|z0|^2, -|z1|^2 }
    __shared__ float4 Ptab[NPAIR][32];      // 16 KB
    __shared__ float4 Qtab[NPAIR][8][2];    //  8 KB
    __shared__ float4 Ztab[NPAIR];          // 512 B
    __shared__ float4 PQtab[NPAIR];         // 512 B

    const int h   = blockIdx.x;
    const int tid = threadIdx.x;

    // ---------------- Setup: one thread per mode (64 threads) ----------------
    if (tid < NMODES) {
        const int n   = tid;
        const int k   = n >> 1;
        const int sub = n & 1;

        const float dt = expf(log_dt[h]);
        const float wr = -expf(log_w_real[h * NMODES + n]);
        const float wi = w_imag[h * NMODES + n];
        const float ar = wr * dt;
        const float ai = wi * dt;

        // z = exp(dtA)
        float s, c;
        const float ez = expf(ar);
        sincosf(ai, &s, &c);
        const float zr = ez * c;
        const float zi = ez * s;

        // 2*Cmod = 2*C*(z-1)/w
        const float den  = wr * wr + wi * wi;
        const float zm1r = zr - 1.0f;
        const float tr = (zm1r * wr + zi * wi) / den;
        const float ti = (zi * wr - zm1r * wi) / den;
        const float cr = C_re[h * NMODES + n];
        const float ci = C_im[h * NMODES + n];
        const float ur = 2.0f * (cr * tr - ci * ti);
        const float ui = 2.0f * (cr * ti + ci * tr);

        // z^8, z^256 via exp (scaled phase args are exact fp32 products)
        float s8, c8, s256, c256;
        const float e8 = expf(ar * 8.0f);
        sincosf(ai * 8.0f, &s8, &c8);
        const float z8r = e8 * c8, z8i = e8 * s8;
        const float e256 = expf(ar * 256.0f);
        sincosf(ai * 256.0f, &s256, &c256);
        const float z256r = e256 * c256, z256i = e256 * s256;

        // scalar tables
        float* zt = reinterpret_cast<float*>(&Ztab[k]);
        zt[sub]     = zr;
        zt[2 + sub] = -zi;
        float* pq = reinterpret_cast<float*>(&PQtab[k]);
        pq[sub]     = zr + zr;
        pq[2 + sub] = -(zr * zr + zi * zi);

        // P table: z^(8r)
        float prc = 1.0f, pic = 0.0f;
        #pragma unroll 1
        for (int r = 0; r < 32; r++) {
            float* pt = reinterpret_cast<float*>(&Ptab[k][r]);
            pt[sub]     = prc;
            pt[2 + sub] = pic;
            const float nr = prc * z8r - pic * z8i;
            const float ni = prc * z8i + pic * z8r;
            prc = nr; pic = ni;
        }

        // Q table: 2*Cmod * z^(256q)
        float qrc = ur, qic = ui;
        #pragma unroll 1
        for (int q = 0; q < 8; q++) {
            float* qt = reinterpret_cast<float*>(&Qtab[k][q][0]);
            qt[sub]     = qrc;
            qt[2 + sub] = qic;
            qt[4 + sub] = -qic;
            const float nr = qrc * z256r - qic * z256i;
            const float ni = qrc * z256i + qic * z256r;
            qrc = nr; qic = ni;
        }
    }
    __syncthreads();

    // ---------------- Main loop: thread owns l in [8*tid, 8*tid+8) ----------------
    const int r  = tid & 31;   // = lane id
    const int qi = tid >> 5;   // warp id (uniform within warp)

    const uint32_t aP  = smem_u32(&Ptab[0][r]);
    const uint32_t aQ  = smem_u32(&Qtab[0][qi][0]);
    const uint32_t aZ  = smem_u32(&Ztab[0]);
    const uint32_t aPQ = smem_u32(&PQtab[0]);

    u64 acc[LPT];
    #pragma unroll
    for (int d = 0; d < LPT; d++) acc[d] = 0ull;

    #pragma unroll 8
    for (int k = 0; k < NPAIR; k++) {
        u64 pr2, pi2, qr2, qi2, qni2, zr2, zni2, pp2, qn2;
        asm("ld.shared.v2.u64 {%0,%1},[%2];" : "=l"(pr2), "=l"(pi2)  : "r"(aP  + k * 512));
        asm("ld.shared.v2.u64 {%0,%1},[%2];" : "=l"(qr2), "=l"(qi2)  : "r"(aQ  + k * 256));
        asm("ld.shared.u64 %0,[%1];"         : "=l"(qni2)            : "r"(aQ  + k * 256 + 16));
        asm("ld.shared.v2.u64 {%0,%1},[%2];" : "=l"(zr2), "=l"(zni2) : "r"(aZ  + k * 16));
        asm("ld.shared.v2.u64 {%0,%1},[%2];" : "=l"(pp2), "=l"(qn2)  : "r"(aPQ + k * 16));

        // anchor A = Q * P  (packed complex mult; both modes of the pair)
        const u64 ar2 = f2fma(qni2, pi2, f2mul(qr2, pr2));   // Qr*Pr - Qi*Pi
        const u64 ai2 = f2fma(qi2,  pr2, f2mul(qr2, pi2));   // Qr*Pi + Qi*Pr

        // x0 = Re(A), x1 = Re(A*z)
        u64 xa = ar2;
        u64 xb = f2fma(ai2, zni2, f2mul(ar2, zr2));

        acc[0] = f2add(acc[0], xa);
        acc[1] = f2add(acc[1], xb);

        // x_{d} = 2Re(z)*x_{d-1} - |z|^2*x_{d-2}
        #pragma unroll
        for (int d = 2; d < LPT; d++) {
            const u64 xn = f2fma(pp2, xb, f2mul(qn2, xa));
            acc[d] = f2add(acc[d], xn);
            xa = xb; xb = xn;
        }
    }

    // ---------------- Epilogue: fold packed halves, coalesced store ----------------
    float res[LPT];
    #pragma unroll
    for (int d = 0; d < LPT; d++) {
        float lo, hi;
        asm("mov.b64 {%0,%1},%2;" : "=f"(lo), "=f"(hi) : "l"(acc[d]));
        res[d] = lo + hi;
    }

    float4* o = reinterpret_cast<float4*>(out + (size_t)h * LLEN + tid * LPT);
    o[0] = make_float4(res[0], res[1], res[2], res[3]);
    o[1] = make_float4(res[4], res[5], res[6], res[7]);
}

extern "C" void kernel_launch(void* const* d_in, const int* in_sizes, int n_in,
                              void* d_out, int out_size)
{
    const float* log_dt     = (const float*)d_in[0];
    const float* log_w_real = (const float*)d_in[1];
    const float* w_imag     = (const float*)d_in[2];
    const float* C_re       = (const float*)d_in[3];
    const float* C_im       = (const float*)d_in[4];
    float*       out        = (float*)d_out;

    ssd_vandermonde_f32x2_kernel<<<HH, TPB>>>(log_dt, log_w_real, w_imag, C_re, C_im, out);
}

// round 3
// speedup vs baseline: 1.5172x; 1.1078x over previous
#include <cuda_runtime.h>
#include <cuda_bf16.h>
#include <cstdint>

#define HH      1024
#define NMODES  64
#define NPAIR   32          // mode pairs
#define LLEN    2048
#define TPB     128         // thread t owns l in [16t, 16t+16)
#define LPT     16          // l per thread

typedef unsigned long long u64;

// ---- packed f32x2 helpers (Blackwell packed fp32) ----
__device__ __forceinline__ u64 f2mul(u64 a, u64 b) {
    u64 d; asm("mul.rn.f32x2 %0,%1,%2;" : "=l"(d) : "l"(a), "l"(b)); return d;
}
__device__ __forceinline__ u64 f2fma(u64 a, u64 b, u64 c) {
    u64 d; asm("fma.rn.f32x2 %0,%1,%2,%3;" : "=l"(d) : "l"(a), "l"(b), "l"(c)); return d;
}
__device__ __forceinline__ u64 f2add(u64 a, u64 b) {
    u64 d; asm("add.rn.f32x2 %0,%1,%2;" : "=l"(d) : "l"(a), "l"(b)); return d;
}
__device__ __forceinline__ uint32_t smem_u32(const void* p) {
    uint32_t a;
    asm("{ .reg .u64 t; cvta.to.shared.u64 t, %1; cvt.u32.u64 %0, t; }" : "=r"(a) : "l"(p));
    return a;
}

__global__ __launch_bounds__(TPB, 6)
void ssd_vandermonde_v3_kernel(
    const float* __restrict__ log_dt,
    const float* __restrict__ log_w_real,
    const float* __restrict__ w_imag,
    const float* __restrict__ C_re,
    const float* __restrict__ C_im,
    float* __restrict__ out)
{
    // Per mode-pair k (modes 2k, 2k+1), packed lo/hi:
    //  Ptab[k][r]  = { Pr0, Pr1, Pi0, Pi1 }                   P  = z^(16r), r = 0..31 (lane)
    //  Qtab[k][q]  = { Qr, -Qi | Q'r, -Q'i } (8 floats)       Q  = 2*Cmod*z^(512q), Q' = Q*z, q = 0..3 (warp)
    //  PQtab[k]    = { 2zr0, 2zr1, -|z0|^2, -|z1|^2 }
    __shared__ float4 Ptab[NPAIR][32];      // 16 KB
    __shared__ float  Qtab[NPAIR][4][8];    //  4 KB
    __shared__ float4 PQtab[NPAIR];         // 512 B

    const int h   = blockIdx.x;
    const int tid = threadIdx.x;

    // ---------------- Setup: one thread per mode (64 threads) ----------------
    if (tid < NMODES) {
        const int n   = tid;
        const int k   = n >> 1;
        const int sub = n & 1;

        const float dt = expf(log_dt[h]);
        const float wr = -expf(log_w_real[h * NMODES + n]);
        const float wi = w_imag[h * NMODES + n];
        const float ar = wr * dt;
        const float ai = wi * dt;

        // z = exp(dtA)
        float s, c;
        const float ez = expf(ar);
        sincosf(ai, &s, &c);
        const float zr = ez * c;
        const float zi = ez * s;

        // 2*Cmod = 2*C*(z-1)/w
        const float den  = wr * wr + wi * wi;
        const float zm1r = zr - 1.0f;
        const float tr = (zm1r * wr + zi * wi) / den;
        const float ti = (zi * wr - zm1r * wi) / den;
        const float cr = C_re[h * NMODES + n];
        const float ci = C_im[h * NMODES + n];
        const float ur = 2.0f * (cr * tr - ci * ti);
        const float ui = 2.0f * (cr * ti + ci * tr);

        // z^16, z^512 via exp (scaled phase args are exact fp32 products)
        float s16, c16, s512, c512;
        const float e16 = expf(ar * 16.0f);
        sincosf(ai * 16.0f, &s16, &c16);
        const float z16r = e16 * c16, z16i = e16 * s16;
        const float e512 = expf(ar * 512.0f);
        sincosf(ai * 512.0f, &s512, &c512);
        const float z512r = e512 * c512, z512i = e512 * s512;

        // recurrence coefficients
        float* pq = reinterpret_cast<float*>(&PQtab[k]);
        pq[sub]     = zr + zr;
        pq[2 + sub] = -(zr * zr + zi * zi);

        // P table: z^(16r)
        float prc = 1.0f, pic = 0.0f;
        #pragma unroll 1
        for (int r = 0; r < 32; r++) {
            float* pt = reinterpret_cast<float*>(&Ptab[k][r]);
            pt[sub]     = prc;
            pt[2 + sub] = pic;
            const float nr = prc * z16r - pic * z16i;
            const float ni = prc * z16i + pic * z16r;
            prc = nr; pic = ni;
        }

        // Q table: Q = 2*Cmod*z^(512q), Q' = Q*z
        float qrc = ur, qic = ui;
        #pragma unroll 1
        for (int q = 0; q < 4; q++) {
            float* qt = &Qtab[k][q][0];
            const float qpr = qrc * zr - qic * zi;   // Q' = Q*z
            const float qpi = qrc * zi + qic * zr;
            qt[sub]     = qrc;
            qt[2 + sub] = -qic;
            qt[4 + sub] = qpr;
            qt[6 + sub] = -qpi;
            const float nr = qrc * z512r - qic * z512i;
            const float ni = qrc * z512i + qic * z512r;
            qrc = nr; qic = ni;
        }
    }
    __syncthreads();

    // ---------------- Main loop: thread owns l in [16*tid, 16*tid+16) ----------------
    const int r  = tid & 31;   // lane -> P index
    const int qi = tid >> 5;   // warp -> Q index (uniform within warp)

    const uint32_t aP  = smem_u32(&Ptab[0][r]);
    const uint32_t aQ  = smem_u32(&Qtab[0][qi][0]);
    const uint32_t aPQ = smem_u32(&PQtab[0]);

    u64 acc[LPT];
    #pragma unroll
    for (int d = 0; d < LPT; d++) acc[d] = 0ull;

    #pragma unroll 4
    for (int k = 0; k < NPAIR; k++) {
        u64 pr2, pi2, qr2, qni2, qpr2, qpni2, pp2, qn2;
        asm("ld.shared.v2.u64 {%0,%1},[%2];" : "=l"(pr2),  "=l"(pi2)   : "r"(aP  + k * 512));
        asm("ld.shared.v2.u64 {%0,%1},[%2];" : "=l"(qr2),  "=l"(qni2)  : "r"(aQ  + k * 128));
        asm("ld.shared.v2.u64 {%0,%1},[%2];" : "=l"(qpr2), "=l"(qpni2) : "r"(aQ  + k * 128 + 16));
        asm("ld.shared.v2.u64 {%0,%1},[%2];" : "=l"(pp2),  "=l"(qn2)   : "r"(aPQ + k * 16));

        // x0 = Re(Q*P), x1 = Re(Q'*P)   (Q' = Q*z precomputed)
        u64 xa = f2fma(qni2,  pi2, f2mul(qr2,  pr2));
        u64 xb = f2fma(qpni2, pi2, f2mul(qpr2, pr2));

        acc[0] = f2add(acc[0], xa);
        acc[1] = f2add(acc[1], xb);

        // x_d = 2Re(z)*x_{d-1} - |z|^2*x_{d-2}
        #pragma unroll
        for (int d = 2; d < LPT; d++) {
            const u64 xn = f2fma(pp2, xb, f2mul(qn2, xa));
            acc[d] = f2add(acc[d], xn);
            xa = xb; xb = xn;
        }
    }

    // ---------------- Epilogue: fold packed halves, coalesced store ----------------
    float res[LPT];
    #pragma unroll
    for (int d = 0; d < LPT; d++) {
        float lo, hi;
        asm("mov.b64 {%0,%1},%2;" : "=f"(lo), "=f"(hi) : "l"(acc[d]));
        res[d] = lo + hi;
    }

    float4* o = reinterpret_cast<float4*>(out + (size_t)h * LLEN + tid * LPT);
    #pragma unroll
    for (int v = 0; v < LPT / 4; v++) {
        o[v] = make_float4(res[4 * v], res[4 * v + 1], res[4 * v + 2], res[4 * v + 3]);
    }
}

extern "C" void kernel_launch(void* const* d_in, const int* in_sizes, int n_in,
                              void* d_out, int out_size)
{
    const float* log_dt     = (const float*)d_in[0];
    const float* log_w_real = (const float*)d_in[1];
    const float* w_imag     = (const float*)d_in[2];
    const float* C_re       = (const float*)d_in[3];
    const float* C_im       = (const float*)d_in[4];
    float*       out        = (float*)d_out;

    ssd_vandermonde_v3_kernel<<<HH, TPB>>>(log_dt, log_w_real, w_imag, C_re, C_im, out);
}

// round 4
// speedup vs baseline: 1.5644x; 1.0311x over previous
#include <cuda_runtime.h>
#include <cuda_bf16.h>
#include <cstdint>

#define HH      1024
#define NMODES  64
#define NPAIR   32          // mode pairs
#define HPAIR   16          // pairs per interleaved set
#define LLEN    2048
#define TPB     128         // thread t owns l in [16t, 16t+16)
#define LPT     16          // l per thread

typedef unsigned long long u64;

// ---- packed f32x2 helpers (Blackwell packed fp32) ----
__device__ __forceinline__ u64 f2mul(u64 a, u64 b) {
    u64 d; asm("mul.rn.f32x2 %0,%1,%2;" : "=l"(d) : "l"(a), "l"(b)); return d;
}
__device__ __forceinline__ u64 f2fma(u64 a, u64 b, u64 c) {
    u64 d; asm("fma.rn.f32x2 %0,%1,%2,%3;" : "=l"(d) : "l"(a), "l"(b), "l"(c)); return d;
}
__device__ __forceinline__ u64 f2add(u64 a, u64 b) {
    u64 d; asm("add.rn.f32x2 %0,%1,%2;" : "=l"(d) : "l"(a), "l"(b)); return d;
}
__device__ __forceinline__ uint32_t smem_u32(const void* p) {
    uint32_t a;
    asm("{ .reg .u64 t; cvta.to.shared.u64 t, %1; cvt.u32.u64 %0, t; }" : "=r"(a) : "l"(p));
    return a;
}

__global__ __launch_bounds__(TPB, 6)
void ssd_vandermonde_v4_kernel(
    const float* __restrict__ log_dt,
    const float* __restrict__ log_w_real,
    const float* __restrict__ w_imag,
    const float* __restrict__ C_re,
    const float* __restrict__ C_im,
    float* __restrict__ out)
{
    // Per mode-pair k (modes 2k, 2k+1), packed lo/hi:
    //  Ptab[k][r]  = { Pr0, Pr1, Pi0, Pi1 }                   P  = z^(16r), r = 0..31 (lane)
    //  Qtab[k][q]  = { Qr, -Qi | Q'r, -Q'i } (8 floats)       Q  = 2*Cmod*z^(512q), Q' = Q*z, q = 0..3 (warp)
    //  PQtab[k]    = { 2zr0, 2zr1, -|z0|^2, -|z1|^2 }
    __shared__ float4 Ptab[NPAIR][32];      // 16 KB
    __shared__ float  Qtab[NPAIR][4][8];    //  4 KB
    __shared__ float4 PQtab[NPAIR];         // 512 B

    const int h   = blockIdx.x;
    const int tid = threadIdx.x;

    // ---------------- Setup: one thread per mode (64 threads) ----------------
    if (tid < NMODES) {
        const int n   = tid;
        const int k   = n >> 1;
        const int sub = n & 1;

        const float dt = expf(log_dt[h]);
        const float wr = -expf(log_w_real[h * NMODES + n]);
        const float wi = w_imag[h * NMODES + n];
        const float ar = wr * dt;
        const float ai = wi * dt;

        // z = exp(dtA)
        float s, c;
        const float ez = expf(ar);
        sincosf(ai, &s, &c);
        const float zr = ez * c;
        const float zi = ez * s;

        // 2*Cmod = 2*C*(z-1)/w
        const float den  = wr * wr + wi * wi;
        const float zm1r = zr - 1.0f;
        const float tr = (zm1r * wr + zi * wi) / den;
        const float ti = (zi * wr - zm1r * wi) / den;
        const float cr = C_re[h * NMODES + n];
        const float ci = C_im[h * NMODES + n];
        const float ur = 2.0f * (cr * tr - ci * ti);
        const float ui = 2.0f * (cr * ti + ci * tr);

        // z^16, z^512 via exp (scaled phase args are exact fp32 products)
        float s16, c16, s512, c512;
        const float e16 = expf(ar * 16.0f);
        sincosf(ai * 16.0f, &s16, &c16);
        const float z16r = e16 * c16, z16i = e16 * s16;
        const float e512 = expf(ar * 512.0f);
        sincosf(ai * 512.0f, &s512, &c512);
        const float z512r = e512 * c512, z512i = e512 * s512;

        // recurrence coefficients
        float* pq = reinterpret_cast<float*>(&PQtab[k]);
        pq[sub]     = zr + zr;
        pq[2 + sub] = -(zr * zr + zi * zi);

        // P table: z^(16r)
        float prc = 1.0f, pic = 0.0f;
        #pragma unroll 1
        for (int r = 0; r < 32; r++) {
            float* pt = reinterpret_cast<float*>(&Ptab[k][r]);
            pt[sub]     = prc;
            pt[2 + sub] = pic;
            const float nr = prc * z16r - pic * z16i;
            const float ni = prc * z16i + pic * z16r;
            prc = nr; pic = ni;
        }

        // Q table: Q = 2*Cmod*z^(512q), Q' = Q*z
        float qrc = ur, qic = ui;
        #pragma unroll 1
        for (int q = 0; q < 4; q++) {
            float* qt = &Qtab[k][q][0];
            const float qpr = qrc * zr - qic * zi;   // Q' = Q*z
            const float qpi = qrc * zi + qic * zr;
            qt[sub]     = qrc;
            qt[2 + sub] = -qic;
            qt[4 + sub] = qpr;
            qt[6 + sub] = -qpi;
            const float nr = qrc * z512r - qic * z512i;
            const float ni = qrc * z512i + qic * z512r;
            qrc = nr; qic = ni;
        }
    }
    __syncthreads();

    // ---------------- Main loop: thread owns l in [16*tid, 16*tid+16) ----------------
    // Two interleaved mode-pair sets (k and k+16) -> two independent FMA chains.
    const int r  = tid & 31;   // lane -> P index
    const int qi = tid >> 5;   // warp -> Q index (uniform within warp)

    const uint32_t aP  = smem_u32(&Ptab[0][r]);
    const uint32_t aQ  = smem_u32(&Qtab[0][qi][0]);
    const uint32_t aPQ = smem_u32(&PQtab[0]);

    u64 acc[LPT];
    #pragma unroll
    for (int d = 0; d < LPT; d++) acc[d] = 0ull;

    #pragma unroll 2
    for (int k = 0; k < HPAIR; k++) {
        // ---- batched loads for both sets (A = pair k, B = pair k+16) ----
        u64 prA, piA, qrA, qniA, qprA, qpniA, ppA, qnA;
        u64 prB, piB, qrB, qniB, qprB, qpniB, ppB, qnB;
        asm("ld.shared.v2.u64 {%0,%1},[%2];" : "=l"(prA),  "=l"(piA)   : "r"(aP  + k * 512));
        asm("ld.shared.v2.u64 {%0,%1},[%2];" : "=l"(prB),  "=l"(piB)   : "r"(aP  + (k + HPAIR) * 512));
        asm("ld.shared.v2.u64 {%0,%1},[%2];" : "=l"(qrA),  "=l"(qniA)  : "r"(aQ  + k * 128));
        asm("ld.shared.v2.u64 {%0,%1},[%2];" : "=l"(qrB),  "=l"(qniB)  : "r"(aQ  + (k + HPAIR) * 128));
        asm("ld.shared.v2.u64 {%0,%1},[%2];" : "=l"(qprA), "=l"(qpniA) : "r"(aQ  + k * 128 + 16));
        asm("ld.shared.v2.u64 {%0,%1},[%2];" : "=l"(qprB), "=l"(qpniB) : "r"(aQ  + (k + HPAIR) * 128 + 16));
        asm("ld.shared.v2.u64 {%0,%1},[%2];" : "=l"(ppA),  "=l"(qnA)   : "r"(aPQ + k * 16));
        asm("ld.shared.v2.u64 {%0,%1},[%2];" : "=l"(ppB),  "=l"(qnB)   : "r"(aPQ + (k + HPAIR) * 16));

        // ---- anchors: x0 = Re(Q*P), x1 = Re(Q'*P) ----
        u64 xaA = f2fma(qniA,  piA, f2mul(qrA,  prA));
        u64 xaB = f2fma(qniB,  piB, f2mul(qrB,  prB));
        u64 xbA = f2fma(qpniA, piA, f2mul(qprA, prA));
        u64 xbB = f2fma(qpniB, piB, f2mul(qprB, prB));

        acc[0] = f2add(f2add(acc[0], xaA), xaB);
        acc[1] = f2add(f2add(acc[1], xbA), xbB);

        // ---- dual interleaved recurrences: x_d = 2Re(z)*x_{d-1} - |z|^2*x_{d-2} ----
        #pragma unroll
        for (int d = 2; d < LPT; d++) {
            const u64 xnA = f2fma(ppA, xbA, f2mul(qnA, xaA));
            const u64 xnB = f2fma(ppB, xbB, f2mul(qnB, xaB));
            acc[d] = f2add(f2add(acc[d], xnA), xnB);
            xaA = xbA; xbA = xnA;
            xaB = xbB; xbB = xnB;
        }
    }

    // ---------------- Epilogue: fold packed halves, coalesced store ----------------
    float res[LPT];
    #pragma unroll
    for (int d = 0; d < LPT; d++) {
        float lo, hi;
        asm("mov.b64 {%0,%1},%2;" : "=f"(lo), "=f"(hi) : "l"(acc[d]));
        res[d] = lo + hi;
    }

    float4* o = reinterpret_cast<float4*>(out + (size_t)h * LLEN + tid * LPT);
    #pragma unroll
    for (int v = 0; v < LPT / 4; v++) {
        o[v] = make_float4(res[4 * v], res[4 * v + 1], res[4 * v + 2], res[4 * v + 3]);
    }
}

extern "C" void kernel_launch(void* const* d_in, const int* in_sizes, int n_in,
                              void* d_out, int out_size)
{
    const float* log_dt     = (const float*)d_in[0];
    const float* log_w_real = (const float*)d_in[1];
    const float* w_imag     = (const float*)d_in[2];
    const float* C_re       = (const float*)d_in[3];
    const float* C_im       = (const float*)d_in[4];
    float*       out        = (float*)d_out;

    ssd_vandermonde_v4_kernel<<<HH, TPB>>>(log_dt, log_w_real, w_imag, C_re, C_im, out);
}